// round 4
// baseline (speedup 1.0000x reference)
#include <cuda_runtime.h>
#include <cstdint>

// ---------------------------------------------------------------------------
// Problem constants
// ---------------------------------------------------------------------------
#define B   16
#define N   64
#define P   128
#define EF  512
#define H   128
#define CH  512
#define M_EDGE (B * N * N)          // 65536 rows
#define G3  (3 * H)                 // 384

// ---------------------------------------------------------------------------
// Scratch (static device globals; no allocation allowed)
// ---------------------------------------------------------------------------
__device__ float g_wihT[H * G3];                 // [128,384] transposed egru_wih
__device__ float g_Wc[EF * G3];                  // fused weight  [512,384]
__device__ float g_bc[G3];                       // fused bias    [384]
__device__ float g_g[(size_t)M_EDGE * G3];       // GRU pre-gates [65536,384]  96 MB
__device__ float g_eh[(size_t)M_EDGE * H];       // edge GRU out  [65536,128]  32 MB
__device__ float g_nh2[B * N * H];               // pooled node states [1024,128]
__device__ float g_a[B * N];                     // per-node attention scalar
__device__ float g_ci[B * P * 2 * H];            // classifier input [2048,256]
__device__ float g_h1[B * P * CH];               // head hidden     [2048,512]
__device__ int   g_pairflag;                     // 1 = int32 pairs, 0 = int64

// ---------------------------------------------------------------------------
// Generic SGEMM: C[M,N] = epi(A[M,K] @ Brm[K,N] + bias)
// Requirements: M%128==0, Ncols%128==0, K%8==0 (all call sites satisfy this)
// 128x128 block tile, BK=8, 256 threads, 8x8 per-thread tile.
// ---------------------------------------------------------------------------
template <bool RELU>
__global__ __launch_bounds__(256) void sgemm_kernel(
    const float* __restrict__ A, const float* __restrict__ Bm,
    const float* __restrict__ bias, float* __restrict__ C,
    int M, int Ncols, int K)
{
    const int BK = 8;
    __shared__ float As[BK][128];
    __shared__ float Bs[BK][128];

    const int bx = blockIdx.x;   // N tile
    const int by = blockIdx.y;   // M tile
    const int tid = threadIdx.x;

    const int tx = tid % 16;     // 16 threads along N
    const int ty = tid / 16;     // 16 threads along M

    float acc[8][8];
#pragma unroll
    for (int i = 0; i < 8; i++)
#pragma unroll
        for (int j = 0; j < 8; j++) acc[i][j] = 0.f;

    const int a_row = tid >> 1;          // 0..127
    const int a_col = (tid & 1) * 4;     // 0 or 4
    const int b_row = tid >> 5;          // 0..7
    const int b_col = (tid & 31) * 4;    // 0..124

    const float* Ab = A + (size_t)by * 128 * K;
    const float* Bb = Bm + bx * 128;

    for (int k0 = 0; k0 < K; k0 += BK) {
        float4 a4 = *(const float4*)(Ab + (size_t)a_row * K + k0 + a_col);
        As[a_col + 0][a_row] = a4.x;
        As[a_col + 1][a_row] = a4.y;
        As[a_col + 2][a_row] = a4.z;
        As[a_col + 3][a_row] = a4.w;
        float4 b4 = *(const float4*)(Bb + (size_t)(k0 + b_row) * Ncols + b_col);
        *(float4*)&Bs[b_row][b_col] = b4;
        __syncthreads();

#pragma unroll
        for (int kk = 0; kk < BK; kk++) {
            float ar[8], br[8];
            float4 t0 = *(const float4*)&As[kk][ty * 8];
            float4 t1 = *(const float4*)&As[kk][ty * 8 + 4];
            ar[0]=t0.x; ar[1]=t0.y; ar[2]=t0.z; ar[3]=t0.w;
            ar[4]=t1.x; ar[5]=t1.y; ar[6]=t1.z; ar[7]=t1.w;
            float4 u0 = *(const float4*)&Bs[kk][tx * 8];
            float4 u1 = *(const float4*)&Bs[kk][tx * 8 + 4];
            br[0]=u0.x; br[1]=u0.y; br[2]=u0.z; br[3]=u0.w;
            br[4]=u1.x; br[5]=u1.y; br[6]=u1.z; br[7]=u1.w;
#pragma unroll
            for (int i = 0; i < 8; i++)
#pragma unroll
                for (int j = 0; j < 8; j++)
                    acc[i][j] = fmaf(ar[i], br[j], acc[i][j]);
        }
        __syncthreads();
    }

    float bl[8];
#pragma unroll
    for (int j = 0; j < 8; j++)
        bl[j] = bias ? bias[bx * 128 + tx * 8 + j] : 0.f;

#pragma unroll
    for (int i = 0; i < 8; i++) {
        float* Crow = C + (size_t)(by * 128 + ty * 8 + i) * Ncols + bx * 128 + tx * 8;
        float4 v0, v1;
        v0.x = acc[i][0] + bl[0]; v0.y = acc[i][1] + bl[1];
        v0.z = acc[i][2] + bl[2]; v0.w = acc[i][3] + bl[3];
        v1.x = acc[i][4] + bl[4]; v1.y = acc[i][5] + bl[5];
        v1.z = acc[i][6] + bl[6]; v1.w = acc[i][7] + bl[7];
        if (RELU) {
            v0.x = fmaxf(v0.x, 0.f); v0.y = fmaxf(v0.y, 0.f);
            v0.z = fmaxf(v0.z, 0.f); v0.w = fmaxf(v0.w, 0.f);
            v1.x = fmaxf(v1.x, 0.f); v1.y = fmaxf(v1.y, 0.f);
            v1.z = fmaxf(v1.z, 0.f); v1.w = fmaxf(v1.w, 0.f);
        }
        *(float4*)(Crow + 0) = v0;
        *(float4*)(Crow + 4) = v1;
    }
}

// ---------------------------------------------------------------------------
// Small helper kernels
// ---------------------------------------------------------------------------
__global__ void transpose_wih_kernel(const float* __restrict__ wih, float* __restrict__ wihT)
{
    int idx = blockIdx.x * blockDim.x + threadIdx.x;   // 128*384
    if (idx < H * G3) {
        int n = idx % G3, k = idx / G3;
        wihT[idx] = wih[n * H + k];
    }
}

__global__ void bc_kernel(const float* __restrict__ et_b, const float* __restrict__ wih,
                          const float* __restrict__ bih, float* __restrict__ bc)
{
    int n = blockIdx.x * blockDim.x + threadIdx.x;
    if (n < G3) {
        float s = bih[n];
        const float* wr = wih + n * H;
#pragma unroll 4
        for (int j = 0; j < H; j++) s = fmaf(et_b[j], wr[j], s);
        bc[n] = s;
    }
}

// GRU gates, float4-vectorized: h = (1 - sigmoid(gz+bz)) * tanh(gn + sigmoid(gr+br)*bn)
// One thread handles 4 consecutive channels of one row -> 3x LDG.128 + 1x STG.128.
__global__ __launch_bounds__(256) void gru_gate_kernel(
    const float* __restrict__ g, const float* __restrict__ bhh,
    float* __restrict__ h)
{
    int idx = blockIdx.x * blockDim.x + threadIdx.x;     // M_EDGE * 32 threads
    if (idx >= M_EDGE * (H / 4)) return;
    int c4 = (idx & 31) * 4;                             // channel group 0,4,...,124
    size_t m = (size_t)(idx >> 5);
    const float* gm = g + m * G3;

    float4 gr = *(const float4*)(gm + c4);
    float4 gz = *(const float4*)(gm + c4 + H);
    float4 gn = *(const float4*)(gm + c4 + 2 * H);
    float4 br = *(const float4*)(bhh + c4);
    float4 bz = *(const float4*)(bhh + c4 + H);
    float4 bn = *(const float4*)(bhh + c4 + 2 * H);

    float4 o;
    {
        float r = 1.f / (1.f + __expf(-(gr.x + br.x)));
        float z = 1.f / (1.f + __expf(-(gz.x + bz.x)));
        o.x = (1.f - z) * tanhf(gn.x + r * bn.x);
    }
    {
        float r = 1.f / (1.f + __expf(-(gr.y + br.y)));
        float z = 1.f / (1.f + __expf(-(gz.y + bz.y)));
        o.y = (1.f - z) * tanhf(gn.y + r * bn.y);
    }
    {
        float r = 1.f / (1.f + __expf(-(gr.z + br.z)));
        float z = 1.f / (1.f + __expf(-(gz.z + bz.z)));
        o.z = (1.f - z) * tanhf(gn.z + r * bn.z);
    }
    {
        float r = 1.f / (1.f + __expf(-(gr.w + br.w)));
        float z = 1.f / (1.f + __expf(-(gz.w + bz.w)));
        o.w = (1.f - z) * tanhf(gn.w + r * bn.w);
    }
    *(float4*)(h + m * H + c4) = o;
}

// Node-attention pooling: nh2[b,i,:] = softmax_j( eh[b,i,j,:] . natt_w[H:2H] ) . eh
__global__ __launch_bounds__(128) void node_pool_kernel(
    const float* __restrict__ eh, const float* __restrict__ natt_w,
    float* __restrict__ nh2)
{
    __shared__ float tile[N * H];     // 32 KB
    __shared__ float logits[N];
    __shared__ float w2s[H];
    __shared__ float red0;

    int bi = blockIdx.x;              // b*64 + i
    int tid = threadIdx.x;            // 128
    const float* ehp = eh + (size_t)bi * N * H;

    w2s[tid] = natt_w[H + tid];
    for (int idx = tid; idx < N * H; idx += 128) tile[idx] = ehp[idx];
    __syncthreads();

    int warp = tid >> 5, lane = tid & 31;
    for (int j = warp; j < N; j += 4) {
        float s = 0.f;
#pragma unroll
        for (int k = lane; k < H; k += 32) s = fmaf(tile[j * H + k], w2s[k], s);
#pragma unroll
        for (int o = 16; o > 0; o >>= 1) s += __shfl_xor_sync(0xffffffffu, s, o);
        if (lane == 0) logits[j] = s;
    }
    __syncthreads();

    if (warp == 0) {
        float m = -1e30f;
        for (int j = lane; j < N; j += 32) m = fmaxf(m, logits[j]);
#pragma unroll
        for (int o = 16; o > 0; o >>= 1) m = fmaxf(m, __shfl_xor_sync(0xffffffffu, m, o));
        float sum = 0.f;
        for (int j = lane; j < N; j += 32) {
            float e = __expf(logits[j] - m);
            logits[j] = e;
            sum += e;
        }
#pragma unroll
        for (int o = 16; o > 0; o >>= 1) sum += __shfl_xor_sync(0xffffffffu, sum, o);
        if (lane == 0) red0 = sum;
    }
    __syncthreads();

    float inv = 1.f / red0;
    float acc = 0.f;
#pragma unroll 8
    for (int j = 0; j < N; j++) acc = fmaf(logits[j], tile[j * H + tid], acc);
    nh2[(size_t)bi * H + tid] = acc * inv;
}

// a[m] = nh2[m,:] . eatt_w[0:H]
__global__ void avec_kernel(const float* __restrict__ nh2, const float* __restrict__ eatt_w,
                            float* __restrict__ a)
{
    int warp = threadIdx.x >> 5, lane = threadIdx.x & 31;
    int m = blockIdx.x * 8 + warp;
    if (m >= B * N) return;
    float s = 0.f;
#pragma unroll
    for (int k = lane; k < H; k += 32) s = fmaf(nh2[(size_t)m * H + k], eatt_w[k], s);
#pragma unroll
    for (int o = 16; o > 0; o >>= 1) s += __shfl_xor_sync(0xffffffffu, s, o);
    if (lane == 0) a[m] = s;
}

// Detect object_pairs dtype layout: int64 (odd 32-bit words all zero) vs int32.
__global__ void detect_pairs_kernel(const int* __restrict__ p)
{
    if (blockIdx.x == 0 && threadIdx.x == 0) {
        int any = 0;
        for (int t = 0; t < 64; t++) any |= p[2 * t + 1];
        g_pairflag = (any != 0) ? 1 : 0;
    }
}

// ci[b,p] = [ 0.5*(nh2[i0]+nh2[i1]),  (1-w)*nh2[i0] + w*nh2[i1] ],  w = sigmoid(a1-a0)
__global__ __launch_bounds__(128) void ci_kernel(
    const float* __restrict__ nh2, const float* __restrict__ a,
    const int* __restrict__ pairs, float* __restrict__ ci)
{
    int row = blockIdx.x;            // b*P + p
    int b = row >> 7;
    int t = threadIdx.x;             // 128
    int i0, i1;
    if (g_pairflag) { i0 = pairs[row * 2 + 0]; i1 = pairs[row * 2 + 1]; }
    else            { i0 = pairs[row * 4 + 0]; i1 = pairs[row * 4 + 2]; }

    const float* n0 = nh2 + ((size_t)b * N + i0) * H;
    const float* n1 = nh2 + ((size_t)b * N + i1) * H;
    float w = 1.f / (1.f + __expf(-(a[b * N + i1] - a[b * N + i0])));
    float v0 = n0[t], v1 = n1[t];
    ci[(size_t)row * 2 * H + t]     = 0.5f * (v0 + v1);
    ci[(size_t)row * 2 * H + H + t] = (1.f - w) * v0 + w * v1;
}

// out[row, off:off+od] = h1[row,:] @ w2 + b2
__global__ __launch_bounds__(128) void head_out_kernel(
    const float* __restrict__ h1, const float* __restrict__ w2,
    const float* __restrict__ b2, float* __restrict__ out, int od, int off)
{
    int row = blockIdx.x;            // 2048
    int warp = threadIdx.x >> 5, lane = threadIdx.x & 31;
    const float* hr = h1 + (size_t)row * CH;
    for (int o = warp; o < od; o += 4) {
        float s = 0.f;
#pragma unroll 4
        for (int k = lane; k < CH; k += 32) s = fmaf(hr[k], w2[k * od + o], s);
#pragma unroll
        for (int sh = 16; sh > 0; sh >>= 1) s += __shfl_xor_sync(0xffffffffu, s, sh);
        if (lane == 0) out[(size_t)row * 14 + off + o] = s + b2[o];
    }
}

// ---------------------------------------------------------------------------
// Launch
// ---------------------------------------------------------------------------
extern "C" void kernel_launch(void* const* d_in, const int* in_sizes, int n_in,
                              void* d_out, int out_size)
{
    // metadata order (reference signature order):
    //  0 x_node(unused) 1 x_edge 2-5 nt_*(unused) 6 et_w 7 et_b
    //  8-10 ngru(unused) 11 egru_wih 12 egru_bih 13 egru_bhh
    // 14 natt_w 15 natt_b(unused) 16 eatt_w 17 eatt_b(unused)
    // 18-21 lr 22-25 cr 26-29 mr 30 object_pairs 31 num_relation(unused)
    const float* x_edge   = (const float*)d_in[1];
    const float* et_w     = (const float*)d_in[6];
    const float* et_b     = (const float*)d_in[7];
    const float* egru_wih = (const float*)d_in[11];
    const float* egru_bih = (const float*)d_in[12];
    const float* egru_bhh = (const float*)d_in[13];
    const float* natt_w   = (const float*)d_in[14];
    const float* eatt_w   = (const float*)d_in[16];
    const float* lr_w1 = (const float*)d_in[18]; const float* lr_b1 = (const float*)d_in[19];
    const float* lr_w2 = (const float*)d_in[20]; const float* lr_b2 = (const float*)d_in[21];
    const float* cr_w1 = (const float*)d_in[22]; const float* cr_b1 = (const float*)d_in[23];
    const float* cr_w2 = (const float*)d_in[24]; const float* cr_b2 = (const float*)d_in[25];
    const float* mr_w1 = (const float*)d_in[26]; const float* mr_b1 = (const float*)d_in[27];
    const float* mr_w2 = (const float*)d_in[28]; const float* mr_b2 = (const float*)d_in[29];
    const int*   pairs = (const int*)d_in[30];
    float* out = (float*)d_out;

    float *wihT, *Wc, *bc, *gbuf, *eh, *nh2, *avec, *ci, *h1;
    cudaGetSymbolAddress((void**)&wihT, g_wihT);
    cudaGetSymbolAddress((void**)&Wc,   g_Wc);
    cudaGetSymbolAddress((void**)&bc,   g_bc);
    cudaGetSymbolAddress((void**)&gbuf, g_g);
    cudaGetSymbolAddress((void**)&eh,   g_eh);
    cudaGetSymbolAddress((void**)&nh2,  g_nh2);
    cudaGetSymbolAddress((void**)&avec, g_a);
    cudaGetSymbolAddress((void**)&ci,   g_ci);
    cudaGetSymbolAddress((void**)&h1,   g_h1);

    // 1. wihT = egru_wih^T   [128,384]
    transpose_wih_kernel<<<(H * G3 + 255) / 256, 256>>>(egru_wih, wihT);
    // 2. Wc = et_w @ wihT    [512,384]
    sgemm_kernel<false><<<dim3(G3 / 128, EF / 128), 256>>>(et_w, wihT, nullptr, Wc, EF, G3, H);
    // 3. bc = et_b @ wihT + egru_bih
    bc_kernel<<<2, 256>>>(et_b, egru_wih, egru_bih, bc);
    // 4. g = x_edge @ Wc + bc   [65536,384]   (the big GEMM, 12.9 GF)
    sgemm_kernel<false><<<dim3(G3 / 128, M_EDGE / 128), 256>>>(x_edge, Wc, bc, gbuf, M_EDGE, G3, EF);
    // 5. eh = GRU gates(g)   [65536,128]  (float4-vectorized)
    gru_gate_kernel<<<(M_EDGE * (H / 4)) / 256, 256>>>(gbuf, egru_bhh, eh);
    // 6. nh2 = softmax-pooled eh over j   [1024,128]
    node_pool_kernel<<<B * N, 128>>>(eh, natt_w, nh2);
    // 7. a[m] = nh2 . eatt_w[:128]
    avec_kernel<<<(B * N) / 8, 256>>>(nh2, eatt_w, avec);
    // 8. pairs dtype probe
    detect_pairs_kernel<<<1, 32>>>(pairs);
    // 9. classifier inputs  [2048,256]
    ci_kernel<<<B * P, 128>>>(nh2, avec, pairs, ci);
    // 10-12. heads: hidden GEMM (relu) then small output projection
    sgemm_kernel<true><<<dim3(CH / 128, (B * P) / 128), 256>>>(ci, lr_w1, lr_b1, h1, B * P, CH, 2 * H);
    head_out_kernel<<<B * P, 128>>>(h1, lr_w2, lr_b2, out, 6, 0);
    sgemm_kernel<true><<<dim3(CH / 128, (B * P) / 128), 256>>>(ci, cr_w1, cr_b1, h1, B * P, CH, 2 * H);
    head_out_kernel<<<B * P, 128>>>(h1, cr_w2, cr_b2, out, 5, 6);
    sgemm_kernel<true><<<dim3(CH / 128, (B * P) / 128), 256>>>(ci, mr_w1, mr_b1, h1, B * P, CH, 2 * H);
    head_out_kernel<<<B * P, 128>>>(h1, mr_w2, mr_b2, out, 3, 11);

    (void)in_sizes; (void)n_in; (void)out_size;
}

// round 11
// speedup vs baseline: 1.3950x; 1.3950x over previous
#include <cuda_runtime.h>
#include <mma.h>
#include <cstdint>

using namespace nvcuda;

// ---------------------------------------------------------------------------
// Problem constants
// ---------------------------------------------------------------------------
#define B   16
#define N   64
#define P   128
#define EF  512
#define H   128
#define CH  512
#define M_EDGE (B * N * N)          // 65536 rows
#define G3  (3 * H)                 // 384

// ---------------------------------------------------------------------------
// Scratch (static device globals; no allocation allowed)
// ---------------------------------------------------------------------------
__device__ float g_etwT[H * EF];                 // et_w^T [128,512]
__device__ float g_WcT[G3 * EF];                 // fused weight [N=384, K=512] row-major
__device__ float g_bc[G3];                       // fused bias [384]
__device__ float g_g[(size_t)M_EDGE * G3];       // GEMM out (pre-gate) [65536,384] 96 MB
__device__ float g_eh[(size_t)M_EDGE * H];       // edge GRU out [65536,128]  32 MB
__device__ float g_nh2[B * N * H];               // pooled node states [1024,128]
__device__ float g_a[B * N];                     // per-node attention scalar
__device__ float g_ci[B * P * 2 * H];            // classifier input [2048,256]
__device__ float g_h1[B * P * CH];               // head hidden [2048,512]
__device__ int   g_pairflag;                     // 1 = int32 pairs, 0 = int64

// Round-to-nearest fp32 -> tf32 (removes truncation bias in MMA inputs)
__device__ __forceinline__ float to_tf32(float x) {
    float y;
    asm("cvt.rna.tf32.f32 %0, %1;" : "=f"(y) : "f"(x));
    return y;
}
__device__ __forceinline__ float4 to_tf32_4(float4 v) {
    v.x = to_tf32(v.x); v.y = to_tf32(v.y);
    v.z = to_tf32(v.z); v.w = to_tf32(v.w);
    return v;
}

// ===========================================================================
// tf32 WMMA GEMM:  C[M,Ncols] = A[M,K] @ Bn[Ncols,K]^T
// A row-major, Bn row-major [N,K] (acts as col-major B).
// 128x128 CTA tile, BK=16, 8 warps, warp tile 64x32 (4x2 wmma 16x16 frags).
// Operands rounded to tf32 during SMEM staging. mma.sync path — plain sm_103.
// ===========================================================================
#define LP 20   // padded SMEM row stride (floats): 80B, float4-aligned

__global__ __launch_bounds__(256) void wmma_gemm_kernel(
    const float* __restrict__ A, const float* __restrict__ Bn,
    float* __restrict__ C, int M, int Ncols, int K)
{
    __shared__ float As[2][128 * LP];
    __shared__ float Bs[2][128 * LP];

    const int bx = blockIdx.x;       // N tile
    const int by = blockIdx.y;       // M tile
    const int tid = threadIdx.x;
    const int wid = tid >> 5;
    const int wm = wid & 1;          // 0..1  (M half: 64 rows)
    const int wn = wid >> 1;         // 0..3  (N quarter: 32 cols)

    wmma::fragment<wmma::accumulator, 16, 16, 8, float> acc[4][2];
#pragma unroll
    for (int i = 0; i < 4; i++)
#pragma unroll
        for (int j = 0; j < 2; j++) wmma::fill_fragment(acc[i][j], 0.f);

    const int nkt = K >> 4;
    for (int kt = 0; kt < nkt; kt++) {
        const int buf = kt & 1;
        // stage A,B tiles: 512 float4 each, 2 per thread
#pragma unroll
        for (int n = 0; n < 2; n++) {
            int f = tid + n * 256;
            int row = f >> 2, c4 = f & 3;
            float4 va = *(const float4*)(A + ((size_t)by * 128 + row) * K + kt * 16 + c4 * 4);
            *(float4*)&As[buf][row * LP + c4 * 4] = to_tf32_4(va);
            float4 vb = *(const float4*)(Bn + ((size_t)bx * 128 + row) * K + kt * 16 + c4 * 4);
            *(float4*)&Bs[buf][row * LP + c4 * 4] = to_tf32_4(vb);
        }
        __syncthreads();

#pragma unroll
        for (int ks = 0; ks < 16; ks += 8) {
            wmma::fragment<wmma::matrix_a, 16, 16, 8, wmma::precision::tf32, wmma::row_major> af[4];
            wmma::fragment<wmma::matrix_b, 16, 16, 8, wmma::precision::tf32, wmma::col_major> bf[2];
#pragma unroll
            for (int i = 0; i < 4; i++)
                wmma::load_matrix_sync(af[i], &As[buf][(wm * 64 + i * 16) * LP + ks], LP);
#pragma unroll
            for (int j = 0; j < 2; j++)
                wmma::load_matrix_sync(bf[j], &Bs[buf][(wn * 32 + j * 16) * LP + ks], LP);
#pragma unroll
            for (int i = 0; i < 4; i++)
#pragma unroll
                for (int j = 0; j < 2; j++)
                    wmma::mma_sync(acc[i][j], af[i], bf[j], acc[i][j]);
        }
        // no trailing sync needed: next iter's sync (after staging other buf)
        // orders compute(kt) before any restage of this buf at kt+2
    }

#pragma unroll
    for (int i = 0; i < 4; i++)
#pragma unroll
        for (int j = 0; j < 2; j++)
            wmma::store_matrix_sync(
                C + ((size_t)by * 128 + wm * 64 + i * 16) * Ncols + bx * 128 + wn * 32 + j * 16,
                acc[i][j], Ncols, wmma::mem_row_major);
}

// ---------------------------------------------------------------------------
// Generic SIMT SGEMM (fp32, small GEMMs + heads): C = epi(A[M,K]@B[K,N]+bias)
// ---------------------------------------------------------------------------
template <bool RELU>
__global__ __launch_bounds__(256) void sgemm_kernel(
    const float* __restrict__ A, const float* __restrict__ Bm,
    const float* __restrict__ bias, float* __restrict__ C,
    int M, int Ncols, int K)
{
    const int BK = 8;
    __shared__ float As[BK][128];
    __shared__ float Bs[BK][128];
    const int bx = blockIdx.x, by = blockIdx.y, tid = threadIdx.x;
    const int tx = tid % 16, ty = tid / 16;
    float acc[8][8];
#pragma unroll
    for (int i = 0; i < 8; i++)
#pragma unroll
        for (int j = 0; j < 8; j++) acc[i][j] = 0.f;
    const int a_row = tid >> 1, a_col = (tid & 1) * 4;
    const int b_row = tid >> 5, b_col = (tid & 31) * 4;
    const float* Ab = A + (size_t)by * 128 * K;
    const float* Bb = Bm + bx * 128;
    for (int k0 = 0; k0 < K; k0 += BK) {
        float4 a4 = *(const float4*)(Ab + (size_t)a_row * K + k0 + a_col);
        As[a_col + 0][a_row] = a4.x; As[a_col + 1][a_row] = a4.y;
        As[a_col + 2][a_row] = a4.z; As[a_col + 3][a_row] = a4.w;
        float4 b4 = *(const float4*)(Bb + (size_t)(k0 + b_row) * Ncols + b_col);
        *(float4*)&Bs[b_row][b_col] = b4;
        __syncthreads();
#pragma unroll
        for (int kk = 0; kk < BK; kk++) {
            float ar[8], br[8];
            float4 t0 = *(const float4*)&As[kk][ty * 8];
            float4 t1 = *(const float4*)&As[kk][ty * 8 + 4];
            ar[0]=t0.x; ar[1]=t0.y; ar[2]=t0.z; ar[3]=t0.w;
            ar[4]=t1.x; ar[5]=t1.y; ar[6]=t1.z; ar[7]=t1.w;
            float4 u0 = *(const float4*)&Bs[kk][tx * 8];
            float4 u1 = *(const float4*)&Bs[kk][tx * 8 + 4];
            br[0]=u0.x; br[1]=u0.y; br[2]=u0.z; br[3]=u0.w;
            br[4]=u1.x; br[5]=u1.y; br[6]=u1.z; br[7]=u1.w;
#pragma unroll
            for (int i = 0; i < 8; i++)
#pragma unroll
                for (int j = 0; j < 8; j++)
                    acc[i][j] = fmaf(ar[i], br[j], acc[i][j]);
        }
        __syncthreads();
    }
    float bl[8];
#pragma unroll
    for (int j = 0; j < 8; j++)
        bl[j] = bias ? bias[bx * 128 + tx * 8 + j] : 0.f;
#pragma unroll
    for (int i = 0; i < 8; i++) {
        float* Crow = C + (size_t)(by * 128 + ty * 8 + i) * Ncols + bx * 128 + tx * 8;
        float4 v0, v1;
        v0.x = acc[i][0] + bl[0]; v0.y = acc[i][1] + bl[1];
        v0.z = acc[i][2] + bl[2]; v0.w = acc[i][3] + bl[3];
        v1.x = acc[i][4] + bl[4]; v1.y = acc[i][5] + bl[5];
        v1.z = acc[i][6] + bl[6]; v1.w = acc[i][7] + bl[7];
        if (RELU) {
            v0.x = fmaxf(v0.x, 0.f); v0.y = fmaxf(v0.y, 0.f);
            v0.z = fmaxf(v0.z, 0.f); v0.w = fmaxf(v0.w, 0.f);
            v1.x = fmaxf(v1.x, 0.f); v1.y = fmaxf(v1.y, 0.f);
            v1.z = fmaxf(v1.z, 0.f); v1.w = fmaxf(v1.w, 0.f);
        }
        *(float4*)(Crow + 0) = v0;
        *(float4*)(Crow + 4) = v1;
    }
}

// ---------------------------------------------------------------------------
// Small helper kernels
// ---------------------------------------------------------------------------
__global__ void transpose_et_kernel(const float* __restrict__ w, float* __restrict__ wT)
{
    int idx = blockIdx.x * blockDim.x + threadIdx.x;   // 128*512
    if (idx < EF * H) {
        int j = idx / EF, k = idx % EF;                // out [128,512]
        wT[idx] = w[k * H + j];
    }
}

__global__ void bc_kernel(const float* __restrict__ et_b, const float* __restrict__ wih,
                          const float* __restrict__ bih, float* __restrict__ bc)
{
    int n = blockIdx.x * blockDim.x + threadIdx.x;
    if (n < G3) {
        float s = bih[n];
        const float* wr = wih + n * H;
#pragma unroll 4
        for (int j = 0; j < H; j++) s = fmaf(et_b[j], wr[j], s);
        bc[n] = s;
    }
}

// GRU gates (float4): h = (1-sigmoid(gz+bcz+bz)) * tanh(gn+bcn + sigmoid(gr+bcr+br)*bn)
__global__ __launch_bounds__(256) void gru_gate_kernel(
    const float* __restrict__ g, const float* __restrict__ bc,
    const float* __restrict__ bhh, float* __restrict__ h)
{
    int idx = blockIdx.x * blockDim.x + threadIdx.x;     // M_EDGE * 32 threads
    if (idx >= M_EDGE * (H / 4)) return;
    int c4 = (idx & 31) * 4;
    size_t m = (size_t)(idx >> 5);
    const float* gm = g + m * G3;

    float4 gr = *(const float4*)(gm + c4);
    float4 gz = *(const float4*)(gm + c4 + H);
    float4 gn = *(const float4*)(gm + c4 + 2 * H);
    float4 cr = *(const float4*)(bc + c4);
    float4 cz = *(const float4*)(bc + c4 + H);
    float4 cn = *(const float4*)(bc + c4 + 2 * H);
    float4 br = *(const float4*)(bhh + c4);
    float4 bz = *(const float4*)(bhh + c4 + H);
    float4 bn = *(const float4*)(bhh + c4 + 2 * H);

    float4 o;
    {
        float r = 1.f / (1.f + __expf(-(gr.x + cr.x + br.x)));
        float z = 1.f / (1.f + __expf(-(gz.x + cz.x + bz.x)));
        o.x = (1.f - z) * tanhf(gn.x + cn.x + r * bn.x);
    }
    {
        float r = 1.f / (1.f + __expf(-(gr.y + cr.y + br.y)));
        float z = 1.f / (1.f + __expf(-(gz.y + cz.y + bz.y)));
        o.y = (1.f - z) * tanhf(gn.y + cn.y + r * bn.y);
    }
    {
        float r = 1.f / (1.f + __expf(-(gr.z + cr.z + br.z)));
        float z = 1.f / (1.f + __expf(-(gz.z + cz.z + bz.z)));
        o.z = (1.f - z) * tanhf(gn.z + cn.z + r * bn.z);
    }
    {
        float r = 1.f / (1.f + __expf(-(gr.w + cr.w + br.w)));
        float z = 1.f / (1.f + __expf(-(gz.w + cz.w + bz.w)));
        o.w = (1.f - z) * tanhf(gn.w + cn.w + r * bn.w);
    }
    *(float4*)(h + m * H + c4) = o;
}

// Node-attention pooling: nh2[b,i,:] = softmax_j( eh[b,i,j,:] . natt_w[H:2H] ) . eh
__global__ __launch_bounds__(128) void node_pool_kernel(
    const float* __restrict__ eh, const float* __restrict__ natt_w,
    float* __restrict__ nh2)
{
    __shared__ float tile[N * H];
    __shared__ float logits[N];
    __shared__ float w2s[H];
    __shared__ float red0;
    int bi = blockIdx.x, tid = threadIdx.x;
    const float* ehp = eh + (size_t)bi * N * H;
    w2s[tid] = natt_w[H + tid];
    for (int idx = tid; idx < N * H; idx += 128) tile[idx] = ehp[idx];
    __syncthreads();
    int warp = tid >> 5, lane = tid & 31;
    for (int j = warp; j < N; j += 4) {
        float s = 0.f;
#pragma unroll
        for (int k = lane; k < H; k += 32) s = fmaf(tile[j * H + k], w2s[k], s);
#pragma unroll
        for (int o = 16; o > 0; o >>= 1) s += __shfl_xor_sync(0xffffffffu, s, o);
        if (lane == 0) logits[j] = s;
    }
    __syncthreads();
    if (warp == 0) {
        float m = -1e30f;
        for (int j = lane; j < N; j += 32) m = fmaxf(m, logits[j]);
#pragma unroll
        for (int o = 16; o > 0; o >>= 1) m = fmaxf(m, __shfl_xor_sync(0xffffffffu, m, o));
        float sum = 0.f;
        for (int j = lane; j < N; j += 32) {
            float e = __expf(logits[j] - m);
            logits[j] = e;
            sum += e;
        }
#pragma unroll
        for (int o = 16; o > 0; o >>= 1) sum += __shfl_xor_sync(0xffffffffu, sum, o);
        if (lane == 0) red0 = sum;
    }
    __syncthreads();
    float inv = 1.f / red0;
    float acc = 0.f;
#pragma unroll 8
    for (int j = 0; j < N; j++) acc = fmaf(logits[j], tile[j * H + tid], acc);
    nh2[(size_t)bi * H + tid] = acc * inv;
}

__global__ void avec_kernel(const float* __restrict__ nh2, const float* __restrict__ eatt_w,
                            float* __restrict__ a)
{
    int warp = threadIdx.x >> 5, lane = threadIdx.x & 31;
    int m = blockIdx.x * 8 + warp;
    if (m >= B * N) return;
    float s = 0.f;
#pragma unroll
    for (int k = lane; k < H; k += 32) s = fmaf(nh2[(size_t)m * H + k], eatt_w[k], s);
#pragma unroll
    for (int o = 16; o > 0; o >>= 1) s += __shfl_xor_sync(0xffffffffu, s, o);
    if (lane == 0) a[m] = s;
}

__global__ void detect_pairs_kernel(const int* __restrict__ p)
{
    if (blockIdx.x == 0 && threadIdx.x == 0) {
        int any = 0;
        for (int t = 0; t < 64; t++) any |= p[2 * t + 1];
        g_pairflag = (any != 0) ? 1 : 0;
    }
}

__global__ __launch_bounds__(128) void ci_kernel(
    const float* __restrict__ nh2, const float* __restrict__ a,
    const int* __restrict__ pairs, float* __restrict__ ci)
{
    int row = blockIdx.x;
    int b = row >> 7;
    int t = threadIdx.x;
    int i0, i1;
    if (g_pairflag) { i0 = pairs[row * 2 + 0]; i1 = pairs[row * 2 + 1]; }
    else            { i0 = pairs[row * 4 + 0]; i1 = pairs[row * 4 + 2]; }
    const float* n0 = nh2 + ((size_t)b * N + i0) * H;
    const float* n1 = nh2 + ((size_t)b * N + i1) * H;
    float w = 1.f / (1.f + __expf(-(a[b * N + i1] - a[b * N + i0])));
    float v0 = n0[t], v1 = n1[t];
    ci[(size_t)row * 2 * H + t]     = 0.5f * (v0 + v1);
    ci[(size_t)row * 2 * H + H + t] = (1.f - w) * v0 + w * v1;
}

__global__ __launch_bounds__(128) void head_out_kernel(
    const float* __restrict__ h1, const float* __restrict__ w2,
    const float* __restrict__ b2, float* __restrict__ out, int od, int off)
{
    int row = blockIdx.x;
    int warp = threadIdx.x >> 5, lane = threadIdx.x & 31;
    const float* hr = h1 + (size_t)row * CH;
    for (int o = warp; o < od; o += 4) {
        float s = 0.f;
#pragma unroll 4
        for (int k = lane; k < CH; k += 32) s = fmaf(hr[k], w2[k * od + o], s);
#pragma unroll
        for (int sh = 16; sh > 0; sh >>= 1) s += __shfl_xor_sync(0xffffffffu, s, sh);
        if (lane == 0) out[(size_t)row * 14 + off + o] = s + b2[o];
    }
}

// ---------------------------------------------------------------------------
// Launch
// ---------------------------------------------------------------------------
extern "C" void kernel_launch(void* const* d_in, const int* in_sizes, int n_in,
                              void* d_out, int out_size)
{
    const float* x_edge   = (const float*)d_in[1];
    const float* et_w     = (const float*)d_in[6];
    const float* et_b     = (const float*)d_in[7];
    const float* egru_wih = (const float*)d_in[11];
    const float* egru_bih = (const float*)d_in[12];
    const float* egru_bhh = (const float*)d_in[13];
    const float* natt_w   = (const float*)d_in[14];
    const float* eatt_w   = (const float*)d_in[16];
    const float* lr_w1 = (const float*)d_in[18]; const float* lr_b1 = (const float*)d_in[19];
    const float* lr_w2 = (const float*)d_in[20]; const float* lr_b2 = (const float*)d_in[21];
    const float* cr_w1 = (const float*)d_in[22]; const float* cr_b1 = (const float*)d_in[23];
    const float* cr_w2 = (const float*)d_in[24]; const float* cr_b2 = (const float*)d_in[25];
    const float* mr_w1 = (const float*)d_in[26]; const float* mr_b1 = (const float*)d_in[27];
    const float* mr_w2 = (const float*)d_in[28]; const float* mr_b2 = (const float*)d_in[29];
    const int*   pairs = (const int*)d_in[30];
    float* out = (float*)d_out;

    float *etwT, *WcT, *bc, *gbuf, *eh, *nh2, *avec, *ci, *h1;
    cudaGetSymbolAddress((void**)&etwT, g_etwT);
    cudaGetSymbolAddress((void**)&WcT,  g_WcT);
    cudaGetSymbolAddress((void**)&bc,   g_bc);
    cudaGetSymbolAddress((void**)&gbuf, g_g);
    cudaGetSymbolAddress((void**)&eh,   g_eh);
    cudaGetSymbolAddress((void**)&nh2,  g_nh2);
    cudaGetSymbolAddress((void**)&avec, g_a);
    cudaGetSymbolAddress((void**)&ci,   g_ci);
    cudaGetSymbolAddress((void**)&h1,   g_h1);

    // 1. et_wT = et_w^T  [128,512]
    transpose_et_kernel<<<(EF * H + 255) / 256, 256>>>(et_w, etwT);
    // 2. WcT = egru_wih @ et_wT  -> [384,512] row-major ([N,K] for the wmma GEMM)
    sgemm_kernel<false><<<dim3(EF / 128, G3 / 128), 256>>>(egru_wih, etwT, nullptr, WcT, G3, EF, H);
    // 3. bc = et_b @ wih^T + egru_bih
    bc_kernel<<<2, 256>>>(et_b, egru_wih, egru_bih, bc);
    // 4. Big GEMM on tensor cores (tf32 wmma): g = x_edge @ WcT^T   [65536,384]
    wmma_gemm_kernel<<<dim3(G3 / 128, M_EDGE / 128), 256>>>(x_edge, WcT, gbuf, M_EDGE, G3, EF);
    // 5. eh = GRU gates(g + bc)   [65536,128]
    gru_gate_kernel<<<(M_EDGE * (H / 4)) / 256, 256>>>(gbuf, bc, egru_bhh, eh);
    // 6. nh2 = softmax-pooled eh over j
    node_pool_kernel<<<B * N, 128>>>(eh, natt_w, nh2);
    // 7. a[m] = nh2 . eatt_w[:128]
    avec_kernel<<<(B * N) / 8, 256>>>(nh2, eatt_w, avec);
    // 8. pairs dtype probe + classifier inputs
    detect_pairs_kernel<<<1, 32>>>(pairs);
    ci_kernel<<<B * P, 128>>>(nh2, avec, pairs, ci);
    // 9. heads (fp32 SIMT to protect the error budget)
    sgemm_kernel<true><<<dim3(CH / 128, (B * P) / 128), 256>>>(ci, lr_w1, lr_b1, h1, B * P, CH, 2 * H);
    head_out_kernel<<<B * P, 128>>>(h1, lr_w2, lr_b2, out, 6, 0);
    sgemm_kernel<true><<<dim3(CH / 128, (B * P) / 128), 256>>>(ci, cr_w1, cr_b1, h1, B * P, CH, 2 * H);
    head_out_kernel<<<B * P, 128>>>(h1, cr_w2, cr_b2, out, 5, 6);
    sgemm_kernel<true><<<dim3(CH / 128, (B * P) / 128), 256>>>(ci, mr_w1, mr_b1, h1, B * P, CH, 2 * H);
    head_out_kernel<<<B * P, 128>>>(h1, mr_w2, mr_b2, out, 3, 11);

    (void)in_sizes; (void)n_in; (void)out_size;
}